// round 12
// baseline (speedup 1.0000x reference)
#include <cuda_runtime.h>
#include <cstdint>

// Shapes (fixed for this problem)
#define BATCH 8
#define NNODE 1024
#define CIN   256
#define HEADS 4
#define DHEAD 64
#define HD    256              // HEADS*DHEAD
#define ROWS  (BATCH*NNODE)    // 8192
#define CAP   128              // max neighbors/row (deg ~ Bin(1024,.05): mean 51)

// Scratch (device globals — no allocation allowed)
__device__ __align__(16) float g_Wx[ROWS * HD];            // 8 MB
__device__ __align__(16) float g_ei[ROWS * HEADS];
__device__ __align__(16) float g_ej[ROWS * HEADS];
__device__ __align__(16) int   g_idx[ROWS * CAP];          // 4 MB
__device__ __align__(16) float g_alpha[ROWS * HEADS * CAP];// 16 MB, [q][h][CAP] UNnormalized
__device__ __align__(16) float g_rz[ROWS * HEADS];         // 1/z per (row, head)
__device__            int   g_deg[ROWS];                   // padded to multiple of 4

__device__ __forceinline__ float leaky(float s) { return s > 0.f ? s : 0.2f * s; }

// packed f32x2 helpers (sm_103a)
#define FMA2(d, a, b) asm("fma.rn.f32x2 %0, %1, %2, %0;" : "+l"(d) : "l"(a), "l"(b))
#define PACKDUP(d, f) asm("mov.b64 %0, {%1, %1};" : "=l"(d) : "r"(__float_as_uint(f)))
#define UNPACK2(lo, hi, v) asm("mov.b64 {%0, %1}, %2;" : "=r"(lo), "=r"(hi) : "l"(v))

// ---------------------------------------------------------------------------
// K1: Wx = X @ W   (8192x256 @ 256x256 fp32)
//     128x64x16 tiles, 256 thr, 8x4 microtile via packed fma.rn.f32x2.
//     Fused epilogue: since the 64-wide N tile == one head, compute
//     e_i[row,head], e_j[row,head] here (width-16 shuffle reduction).
// ---------------------------------------------------------------------------
__global__ __launch_bounds__(256) void k_gemm(const float* __restrict__ X,
                                              const float* __restrict__ W,
                                              const float* __restrict__ a) {
    __shared__ __align__(16) float As[16][134];  // [k][m], 8B-aligned rows
    __shared__ __align__(16) float Bs[16][64];   // [k][n]
    const int bm = blockIdx.x * 128;
    const int head = blockIdx.y;
    const int bn = head * 64;
    const int tid = threadIdx.x;
    const int tx = tid & 15, ty = tid >> 4;       // n-group, m-group
    const int ar = tid >> 1, ac = (tid & 1) << 3; // X loader: row, k-col (0 or 8)
    const int br = tid >> 4, bc = (tid & 15) << 2;

    unsigned long long acc[4][4];                 // [m-pair][n], each = 2 fp32 along m
#pragma unroll
    for (int p = 0; p < 4; p++)
#pragma unroll
        for (int j = 0; j < 4; j++) acc[p][j] = 0ull;

    for (int k0 = 0; k0 < CIN; k0 += 16) {
        float4 x0 = *(const float4*)(X + (size_t)(bm + ar) * CIN + k0 + ac);
        float4 x1 = *(const float4*)(X + (size_t)(bm + ar) * CIN + k0 + ac + 4);
        As[ac + 0][ar] = x0.x; As[ac + 1][ar] = x0.y;
        As[ac + 2][ar] = x0.z; As[ac + 3][ar] = x0.w;
        As[ac + 4][ar] = x1.x; As[ac + 5][ar] = x1.y;
        As[ac + 6][ar] = x1.z; As[ac + 7][ar] = x1.w;
        *(float4*)&Bs[br][bc] = *(const float4*)(W + (size_t)(k0 + br) * HD + bn + bc);
        __syncthreads();
#pragma unroll
        for (int k = 0; k < 16; k++) {
            unsigned long long a0 = *(const unsigned long long*)&As[k][(ty << 3) + 0];
            unsigned long long a1 = *(const unsigned long long*)&As[k][(ty << 3) + 2];
            unsigned long long a2 = *(const unsigned long long*)&As[k][(ty << 3) + 4];
            unsigned long long a3 = *(const unsigned long long*)&As[k][(ty << 3) + 6];
            float4 b = *(const float4*)&Bs[k][tx << 2];
            unsigned long long bb0, bb1, bb2, bb3;
            PACKDUP(bb0, b.x); PACKDUP(bb1, b.y);
            PACKDUP(bb2, b.z); PACKDUP(bb3, b.w);
            FMA2(acc[0][0], a0, bb0); FMA2(acc[0][1], a0, bb1);
            FMA2(acc[0][2], a0, bb2); FMA2(acc[0][3], a0, bb3);
            FMA2(acc[1][0], a1, bb0); FMA2(acc[1][1], a1, bb1);
            FMA2(acc[1][2], a1, bb2); FMA2(acc[1][3], a1, bb3);
            FMA2(acc[2][0], a2, bb0); FMA2(acc[2][1], a2, bb1);
            FMA2(acc[2][2], a2, bb2); FMA2(acc[2][3], a2, bb3);
            FMA2(acc[3][0], a3, bb0); FMA2(acc[3][1], a3, bb1);
            FMA2(acc[3][2], a3, bb2); FMA2(acc[3][3], a3, bb3);
        }
        __syncthreads();
    }

    // --- store Wx tile ---
#pragma unroll
    for (int p = 0; p < 4; p++) {
        unsigned l0, h0, l1, h1, l2, h2, l3, h3;
        UNPACK2(l0, h0, acc[p][0]); UNPACK2(l1, h1, acc[p][1]);
        UNPACK2(l2, h2, acc[p][2]); UNPACK2(l3, h3, acc[p][3]);
        const size_t r0 = (size_t)(bm + (ty << 3) + (p << 1)) * HD + bn + (tx << 2);
        *(float4*)(g_Wx + r0)      = make_float4(__uint_as_float(l0), __uint_as_float(l1),
                                                 __uint_as_float(l2), __uint_as_float(l3));
        *(float4*)(g_Wx + r0 + HD) = make_float4(__uint_as_float(h0), __uint_as_float(h1),
                                                 __uint_as_float(h2), __uint_as_float(h3));
    }

    // --- fused e_i / e_j for this head (reduce over tx = 16 lanes) ---
    {
        const float4 ai4 = *(const float4*)(a + head * 128 + (tx << 2));
        const float4 aj4 = *(const float4*)(a + head * 128 + 64 + (tx << 2));
        unsigned long long dx, dy, dz, dw, ex, ey, ez, ew;
        PACKDUP(dx, ai4.x); PACKDUP(dy, ai4.y); PACKDUP(dz, ai4.z); PACKDUP(dw, ai4.w);
        PACKDUP(ex, aj4.x); PACKDUP(ey, aj4.y); PACKDUP(ez, aj4.z); PACKDUP(ew, aj4.w);
#pragma unroll
        for (int p = 0; p < 4; p++) {
            unsigned long long si = 0ull, sj = 0ull;
            FMA2(si, acc[p][0], dx); FMA2(si, acc[p][1], dy);
            FMA2(si, acc[p][2], dz); FMA2(si, acc[p][3], dw);
            FMA2(sj, acc[p][0], ex); FMA2(sj, acc[p][1], ey);
            FMA2(sj, acc[p][2], ez); FMA2(sj, acc[p][3], ew);
            unsigned il, ih, jl, jh;
            UNPACK2(il, ih, si); UNPACK2(jl, jh, sj);
            float eil = __uint_as_float(il), eih = __uint_as_float(ih);
            float ejl = __uint_as_float(jl), ejh = __uint_as_float(jh);
#pragma unroll
            for (int off = 8; off > 0; off >>= 1) {
                eil += __shfl_down_sync(0xffffffffu, eil, off, 16);
                eih += __shfl_down_sync(0xffffffffu, eih, off, 16);
                ejl += __shfl_down_sync(0xffffffffu, ejl, off, 16);
                ejh += __shfl_down_sync(0xffffffffu, ejh, off, 16);
            }
            if (tx == 0) {
                const int row = bm + (ty << 3) + (p << 1);
                g_ei[(size_t)row * HEADS + head]       = eil;
                g_ei[(size_t)(row + 1) * HEADS + head] = eih;
                g_ej[(size_t)row * HEADS + head]       = ejl;
                g_ej[(size_t)(row + 1) * HEADS + head] = ejh;
            }
        }
    }
}

// ---------------------------------------------------------------------------
// K3: single-pass CSR build. Write idx + UNnormalized exp scores (per-head
//     planes [q][h][CAP]); accumulate z; pad list to multiple of 4 with
//     alpha=0 entries; store 1/z.
// ---------------------------------------------------------------------------
__global__ __launch_bounds__(256) void k_build(const float* __restrict__ adj) {
    const int warp = threadIdx.x >> 5;
    const int lane = threadIdx.x & 31;
    const int gw = blockIdx.x * 8 + warp;      // query row
    const int b = gw >> 10, n = gw & 1023;

    const float e0 = g_ei[gw * 4 + 0], e1 = g_ei[gw * 4 + 1];
    const float e2 = g_ei[gw * 4 + 2], e3 = g_ei[gw * 4 + 3];
    const float* arow = adj + (size_t)gw * NNODE;
    const float4* ej4 = (const float4*)(g_ej + ((size_t)b << 10) * HEADS);
    int* __restrict__ gidx = g_idx + (size_t)gw * CAP;
    float* __restrict__ gal = g_alpha + (size_t)gw * HEADS * CAP;

    float z0 = 0.f, z1 = 0.f, z2 = 0.f, z3 = 0.f;
    int pos = 0;
    const unsigned lmask = (1u << lane) - 1u;

    for (int j0 = 0; j0 < NNODE; j0 += 32) {
        const int j = j0 + lane;
        const float av = arow[j];
        const bool act = (av != 0.f) || (j == n);
        const unsigned bal = __ballot_sync(0xffffffffu, act);
        if (act) {
            const int p = pos + __popc(bal & lmask);
            float4 ev = ej4[j];
            const float px = __expf(leaky(e0 + ev.x));
            const float py = __expf(leaky(e1 + ev.y));
            const float pz = __expf(leaky(e2 + ev.z));
            const float pw = __expf(leaky(e3 + ev.w));
            z0 += px; z1 += py; z2 += pz; z3 += pw;
            if (p < CAP) {
                gidx[p] = j;
                gal[p]           = px;
                gal[CAP + p]     = py;
                gal[2 * CAP + p] = pz;
                gal[3 * CAP + p] = pw;
            }
        }
        pos += __popc(bal);
    }
#pragma unroll
    for (int off = 16; off > 0; off >>= 1) {
        z0 += __shfl_xor_sync(0xffffffffu, z0, off);
        z1 += __shfl_xor_sync(0xffffffffu, z1, off);
        z2 += __shfl_xor_sync(0xffffffffu, z2, off);
        z3 += __shfl_xor_sync(0xffffffffu, z3, off);
    }
    const int deg = min(pos, CAP);
    const int deg4 = (deg + 3) & ~3;
    if (lane < deg4 - deg) {               // pad with zero-alpha self entries
        const int p = deg + lane;
        gidx[p] = n;
        gal[p] = 0.f; gal[CAP + p] = 0.f; gal[2 * CAP + p] = 0.f; gal[3 * CAP + p] = 0.f;
    }
    if (lane == 0) {
        g_deg[gw] = deg4;
        g_rz[gw * 4 + 0] = 1.f / z0;
        g_rz[gw * 4 + 1] = 1.f / z1;
        g_rz[gw * 4 + 2] = 1.f / z2;
        g_rz[gw * 4 + 3] = 1.f / z3;
    }
}

// ---------------------------------------------------------------------------
// K4: sparse aggregation — 2 warps/query (channel halves), 4 neighbors/iter.
//     Per batch of 4: int4 idx + float4 alpha (uniform) + 4 indep LDG.128.
// ---------------------------------------------------------------------------
__global__ __launch_bounds__(256) void k_agg(float* __restrict__ out) {
    const int gw2 = (blockIdx.x * blockDim.x + threadIdx.x) >> 5;  // 0..16383
    const int lane = threadIdx.x & 31;
    const int q = gw2 >> 1;           // query row
    const int half = gw2 & 1;
    const int b = q >> 10;
    const int ch = (half << 7) + (lane << 2);   // channel base (float4)
    const int myhead = ch >> 6;                 // 0..3

    const int deg4 = g_deg[q];
    const int4*  __restrict__ idx4 = (const int4*)(g_idx + (size_t)q * CAP);
    const float4* __restrict__ al4 = (const float4*)(g_alpha + ((size_t)q * HEADS + myhead) * CAP);
    const float* __restrict__ wb = g_Wx + (((size_t)b << 10)) * HD + ch;

    float a0 = 0.f, a1 = 0.f, a2 = 0.f, a3 = 0.f;

#pragma unroll 2
    for (int k = 0; k < deg4; k += 4) {
        const int4  jv = idx4[k >> 2];
        const float4 p = al4[k >> 2];
        const float4 w0 = *(const float4*)(wb + (size_t)jv.x * HD);
        const float4 w1 = *(const float4*)(wb + (size_t)jv.y * HD);
        const float4 w2 = *(const float4*)(wb + (size_t)jv.z * HD);
        const float4 w3 = *(const float4*)(wb + (size_t)jv.w * HD);
        a0 = fmaf(p.x, w0.x, a0); a1 = fmaf(p.x, w0.y, a1);
        a2 = fmaf(p.x, w0.z, a2); a3 = fmaf(p.x, w0.w, a3);
        a0 = fmaf(p.y, w1.x, a0); a1 = fmaf(p.y, w1.y, a1);
        a2 = fmaf(p.y, w1.z, a2); a3 = fmaf(p.y, w1.w, a3);
        a0 = fmaf(p.z, w2.x, a0); a1 = fmaf(p.z, w2.y, a1);
        a2 = fmaf(p.z, w2.z, a2); a3 = fmaf(p.z, w2.w, a3);
        a0 = fmaf(p.w, w3.x, a0); a1 = fmaf(p.w, w3.y, a1);
        a2 = fmaf(p.w, w3.z, a2); a3 = fmaf(p.w, w3.w, a3);
    }

    const float rz = g_rz[q * 4 + myhead];
    *(float4*)(out + (size_t)q * HD + ch) =
        make_float4(a0 * rz, a1 * rz, a2 * rz, a3 * rz);
}

// ---------------------------------------------------------------------------
extern "C" void kernel_launch(void* const* d_in, const int* in_sizes, int n_in,
                              void* d_out, int out_size) {
    const float* x   = (const float*)d_in[0];   // (8,1024,256)
    const float* adj = (const float*)d_in[1];   // (8,1024,1024)
    const float* W   = (const float*)d_in[2];   // (256,256)
    const float* a   = (const float*)d_in[3];   // (1,4,128)
    float* out = (float*)d_out;                 // (8,1024,256)

    dim3 gg(ROWS / 128, HD / 64);               // 64 x 4
    k_gemm<<<gg, 256>>>(x, W, a);               // Wx + fused e_i/e_j
    k_build<<<ROWS / 8, 256>>>(adj);            // warp per row
    k_agg<<<ROWS * 2 / 8, 256>>>(out);          // 2 warps per query, 2048 blocks
}